// round 1
// baseline (speedup 1.0000x reference)
#include <cuda_runtime.h>

#define T_DIM 2048
#define NI    4096
#define L     32
#define F     16

typedef unsigned long long ull;

// Normalized weights staging buffer (device global: no allocs allowed)
__device__ float g_wn[L * F];

__device__ __forceinline__ ull ffma2(ull a, ull b, ull c) {
    ull d;
    asm("fma.rn.f32x2 %0, %1, %2, %3;" : "=l"(d) : "l"(a), "l"(b), "l"(c));
    return d;
}

__device__ __forceinline__ ull pack2(float x) {
    ull d;
    asm("mov.b64 %0, {%1, %1};" : "=l"(d) : "f"(x));
    return d;
}

// Tiny prep: pos-constraint + L2-normalize weights over the lag axis.
__global__ void prep_kernel(const float* __restrict__ w) {
    int f = threadIdx.x;
    if (f < F) {
        float col[L];
        float s = 0.f;
#pragma unroll
        for (int j = 0; j < L; j++) {
            float v = fmaxf(w[j * F + f], 0.f);
            col[j] = v;
            s += v * v;
        }
        float inv = rsqrtf(fmaxf(s, 1e-12f));
#pragma unroll
        for (int j = 0; j < L; j++) g_wn[j * F + f] = col[j] * inv;
    }
}

// Main kernel: each thread computes 4 consecutive t for one input channel i,
// all 16 filters, using packed f32x2 FMAs. Block = 128 i-lanes x 2 t-groups.
__global__ __launch_bounds__(256) void conv_kernel(const float* __restrict__ x,
                                                   const float* __restrict__ bias,
                                                   float* __restrict__ out) {
    __shared__ ull sw[L * F / 2];  // 256 packed weight pairs
    __shared__ ull sb[F / 2];      // packed bias pairs

    int tid = threadIdx.x;
    const ull* gw = reinterpret_cast<const ull*>(g_wn);
    sw[tid] = gw[tid];  // exactly 256 threads, 256 pairs
    if (tid < F / 2) sb[tid] = reinterpret_cast<const ull*>(bias)[tid];
    __syncthreads();

    const int i  = blockIdx.x * 128 + (tid & 127);
    const int t0 = blockIdx.y * 8 + (tid >> 7) * 4;

    // Accumulators initialized with bias (folds the bias add for free)
    ull acc[4][8];
#pragma unroll
    for (int r = 0; r < 4; r++)
#pragma unroll
        for (int p = 0; p < 8; p++) acc[r][p] = sb[p];

    const float* xi = x + i;

    // Sliding register window: xw[r] = x[t0 + r - 1 - 2j, i]
    float xw[4];
#pragma unroll
    for (int r = 0; r < 4; r++) {
        int idx = t0 - 1 + r;  // max 2046 < T_DIM, only low edge needs guard
        xw[r] = (idx >= 0) ? xi[(long)idx * NI] : 0.f;
    }

#pragma unroll
    for (int j = 0; j < L; j++) {
        // Prefetch the 2 fresh x values needed by lag j+1
        float n0 = 0.f, n1 = 0.f;
        if (j < L - 1) {
            int b = t0 - 3 - 2 * j;
            if (b >= 0)     n0 = xi[(long)b * NI];
            if (b + 1 >= 0) n1 = xi[(long)(b + 1) * NI];
        }

        ull w[8];
#pragma unroll
        for (int p = 0; p < 8; p++) w[p] = sw[j * 8 + p];  // broadcast LDS.64

#pragma unroll
        for (int r = 0; r < 4; r++) {
            ull xp = pack2(xw[r]);
#pragma unroll
            for (int p = 0; p < 8; p++) acc[r][p] = ffma2(xp, w[p], acc[r][p]);
        }

        // shift window down by 2 time steps (j -> j+1)
        xw[3] = xw[1];
        xw[2] = xw[0];
        xw[1] = n1;
        xw[0] = n0;
    }

    // Epilogue: ReLU + vectorized store (16 contiguous floats per (t,i))
#pragma unroll
    for (int r = 0; r < 4; r++) {
        float4 v[4];
        const float* af = reinterpret_cast<const float*>(acc[r]);
        float* vf = reinterpret_cast<float*>(v);
#pragma unroll
        for (int k = 0; k < 16; k++) vf[k] = fmaxf(af[k], 0.f);
        float4* o = reinterpret_cast<float4*>(out + (long)(t0 + r) * (NI * F) + i * F);
        o[0] = v[0];
        o[1] = v[1];
        o[2] = v[2];
        o[3] = v[3];
    }
}

extern "C" void kernel_launch(void* const* d_in, const int* in_sizes, int n_in,
                              void* d_out, int out_size) {
    const float* x    = (const float*)d_in[0];
    const float* w    = (const float*)d_in[1];
    const float* bias = (const float*)d_in[2];
    float* out        = (float*)d_out;

    prep_kernel<<<1, 32>>>(w);

    dim3 grid(NI / 128, T_DIM / 8);
    conv_kernel<<<grid, 256>>>(x, bias, out);
}

// round 2
// speedup vs baseline: 1.1067x; 1.1067x over previous
#include <cuda_runtime.h>

#define T_DIM 2048
#define NI    4096
#define L     32
#define F     16

typedef unsigned long long ull;

__device__ float g_wn[L * F];

__device__ __forceinline__ ull ffma2(ull a, ull b, ull c) {
    ull d;
    asm("fma.rn.f32x2 %0, %1, %2, %3;" : "=l"(d) : "l"(a), "l"(b), "l"(c));
    return d;
}

__device__ __forceinline__ ull pack2(float x) {
    ull d;
    asm("mov.b64 %0, {%1, %1};" : "=l"(d) : "f"(x));
    return d;
}

// pos-constraint + L2-normalize weights over lag axis
__global__ void prep_kernel(const float* __restrict__ w) {
    int f = threadIdx.x;
    if (f < F) {
        float col[L];
        float s = 0.f;
#pragma unroll
        for (int j = 0; j < L; j++) {
            float v = fmaxf(w[j * F + f], 0.f);
            col[j] = v;
            s += v * v;
        }
        float inv = rsqrtf(fmaxf(s, 1e-12f));
#pragma unroll
        for (int j = 0; j < L; j++) g_wn[j * F + f] = col[j] * inv;
    }
}

// Each thread: 8 consecutive t, 8 filters (half of F), one input channel i.
// Block = 128 i-lanes x 2 filter-halves. Per lag: 4 LDS.64 (weights),
// 32 FFMA2, ~2 LDG prefetched 3 lags ahead.
__global__ __launch_bounds__(256) void conv_kernel(const float* __restrict__ x,
                                                   const float* __restrict__ bias,
                                                   float* __restrict__ out) {
    __shared__ ull sw[L * F / 2];  // 256 packed weight pairs
    __shared__ ull sb[F / 2];

    const int tid = threadIdx.x;
    sw[tid] = reinterpret_cast<const ull*>(g_wn)[tid];
    if (tid < F / 2) sb[tid] = reinterpret_cast<const ull*>(bias)[tid];
    __syncthreads();

    const int lane = tid & 127;
    const int fh   = tid >> 7;            // 0 or 1: filter half
    const int i    = blockIdx.x * 128 + lane;
    const int t0   = blockIdx.y * 8;

    const float* xi = x + i;

    // acc[t-row][filter-pair], init with bias
    ull acc[8][4];
#pragma unroll
    for (int r = 0; r < 8; r++)
#pragma unroll
        for (int p = 0; p < 4; p++) acc[r][p] = sb[fh * 4 + p];

    // sliding window for lag 0: xw[r] = x[t0 + r - 1]
    float xw[8];
#pragma unroll
    for (int r = 0; r < 8; r++) {
        int idx = t0 - 1 + r;             // max 2046 < T_DIM
        xw[r] = (idx >= 0) ? xi[(long)idx * NI] : 0.f;
    }

    // 3-deep prefetch pipeline: fA = fresh pair for lag j+1, fB for j+2
    float fA0, fA1, fB0, fB1;
    {
        int b = t0 - 3;
        fA0 = (b >= 0)     ? xi[(long)b * NI]       : 0.f;
        fA1 = (b + 1 >= 0) ? xi[(long)(b + 1) * NI] : 0.f;
    }
    {
        int b = t0 - 5;
        fB0 = (b >= 0)     ? xi[(long)b * NI]       : 0.f;
        fB1 = (b + 1 >= 0) ? xi[(long)(b + 1) * NI] : 0.f;
    }

#pragma unroll
    for (int j = 0; j < L; j++) {
        // issue loads for lag j+3 (consumed ~160 issue slots later)
        float fC0 = 0.f, fC1 = 0.f;
        if (j < L - 3) {
            int b = t0 - 7 - 2 * j;
            if (b >= 0)     fC0 = xi[(long)b * NI];
            if (b + 1 >= 0) fC1 = xi[(long)(b + 1) * NI];
        }

        ull w[4];
#pragma unroll
        for (int p = 0; p < 4; p++) w[p] = sw[j * 8 + fh * 4 + p];

#pragma unroll
        for (int r = 0; r < 8; r++) {
            ull xp = pack2(xw[r]);
#pragma unroll
            for (int p = 0; p < 4; p++) acc[r][p] = ffma2(xp, w[p], acc[r][p]);
        }

        // shift window by 2 time steps (register renames under full unroll)
#pragma unroll
        for (int r = 7; r >= 2; r--) xw[r] = xw[r - 2];
        xw[1] = fA1; xw[0] = fA0;
        fA0 = fB0; fA1 = fB1;
        fB0 = fC0; fB1 = fC1;
    }

    // ReLU + vectorized store: 8 floats per (t, i, filter-half)
#pragma unroll
    for (int r = 0; r < 8; r++) {
        float4 v[2];
        float* vf = reinterpret_cast<float*>(v);
        const float* af = reinterpret_cast<const float*>(acc[r]);
#pragma unroll
        for (int k = 0; k < 8; k++) vf[k] = fmaxf(af[k], 0.f);
        float4* o = reinterpret_cast<float4*>(out + (long)(t0 + r) * (NI * F) + i * F + fh * 8);
        o[0] = v[0];
        o[1] = v[1];
    }
}

extern "C" void kernel_launch(void* const* d_in, const int* in_sizes, int n_in,
                              void* d_out, int out_size) {
    const float* x    = (const float*)d_in[0];
    const float* w    = (const float*)d_in[1];
    const float* bias = (const float*)d_in[2];
    float* out        = (float*)d_out;

    prep_kernel<<<1, 32>>>(w);

    dim3 grid(NI / 128, T_DIM / 8);
    conv_kernel<<<grid, 256>>>(x, bias, out);
}

// round 3
// speedup vs baseline: 1.1326x; 1.0234x over previous
#include <cuda_runtime.h>

#define T_DIM 2048
#define NI    4096
#define L     32
#define F     16
#define NROWS 72          // window rows: t0-65 .. t0+6

typedef unsigned long long ull;

__device__ float g_wn[L * F];

__device__ __forceinline__ ull ffma2(ull a, ull b, ull c) {
    ull d;
    asm("fma.rn.f32x2 %0, %1, %2, %3;" : "=l"(d) : "l"(a), "l"(b), "l"(c));
    return d;
}

__device__ __forceinline__ ull pack2(float x) {
    ull d;
    asm("mov.b64 %0, {%1, %1};" : "=l"(d) : "f"(x));
    return d;
}

// pos-constraint + L2-normalize weights over lag axis
__global__ void prep_kernel(const float* __restrict__ w) {
    int f = threadIdx.x;
    if (f < F) {
        float col[L];
        float s = 0.f;
#pragma unroll
        for (int j = 0; j < L; j++) {
            float v = fmaxf(w[j * F + f], 0.f);
            col[j] = v;
            s += v * v;
        }
        float inv = rsqrtf(fmaxf(s, 1e-12f));
#pragma unroll
        for (int j = 0; j < L; j++) g_wn[j * F + f] = col[j] * inv;
    }
}

// Block: 128 i-lanes x 2 filter-halves (256 thr). Each thread: 8 t x 8 f.
// Entire x window staged to smem via cp.async (zero-filled for t<0), so the
// hot loop has only smem dependencies (LDS ~29cyc, hidden by FMA chain).
__global__ __launch_bounds__(256) void conv_kernel(const float* __restrict__ x,
                                                   const float* __restrict__ bias,
                                                   float* __restrict__ out) {
    __shared__ float sx[NROWS * 128];   // 36 KB x window
    __shared__ ull   sw[L * F / 2];     // 2 KB packed weights
    __shared__ ull   sb[F / 2];

    const int tid  = threadIdx.x;
    const int lane = tid & 127;
    const int fh   = tid >> 7;
    const int t0   = blockIdx.y * 8;
    const int ib   = blockIdx.x * 128;

    // ---- stage x window: rows g = t0-65+row for row in [0,72) ----
    {
        unsigned sx_u = (unsigned)__cvta_generic_to_shared(sx);
#pragma unroll
        for (int k = 0; k < 9; k++) {
            int c    = tid + k * 256;        // 0..2303 chunks of 16B
            int row  = c >> 5;
            int col  = (c & 31) * 4;         // float index within row
            int g    = t0 - 65 + row;
            unsigned dst = sx_u + (unsigned)(row * 128 + col) * 4u;
            const float* src = x + (long)max(g, 0) * NI + ib + col;
            int sz = (g >= 0) ? 16 : 0;      // zero-fill negative-t rows
            asm volatile("cp.async.cg.shared.global [%0], [%1], 16, %2;"
                         :: "r"(dst), "l"(src), "r"(sz));
        }
        asm volatile("cp.async.commit_group;");
    }

    // weights + bias into smem
    sw[tid] = reinterpret_cast<const ull*>(g_wn)[tid];
    if (tid < F / 2) sb[tid] = reinterpret_cast<const ull*>(bias)[tid];

    asm volatile("cp.async.wait_group 0;");
    __syncthreads();

    // ---- compute ----
    ull acc[8][4];
#pragma unroll
    for (int r = 0; r < 8; r++)
#pragma unroll
        for (int p = 0; p < 4; p++) acc[r][p] = sb[fh * 4 + p];

    const float* sxf = sx + lane;   // column for this thread's i

    // window for lag 0: xw[r] = x[t0-1+r] = smem row 64+r
    float xw[8];
#pragma unroll
    for (int r = 0; r < 8; r++) xw[r] = sxf[(64 + r) * 128];

    // preload lag-0 weights
    ull wcur[4];
#pragma unroll
    for (int p = 0; p < 4; p++) wcur[p] = sw[fh * 4 + p];

#pragma unroll
    for (int j = 0; j < L; j++) {
        // prefetch next lag's weights + fresh x pair (smem rows 62-2j, 63-2j)
        ull   wnext[4];
        float n0 = 0.f, n1 = 0.f;
        if (j < L - 1) {
#pragma unroll
            for (int p = 0; p < 4; p++) wnext[p] = sw[(j + 1) * 8 + fh * 4 + p];
            n0 = sxf[(62 - 2 * j) * 128];
            n1 = sxf[(63 - 2 * j) * 128];
        }

#pragma unroll
        for (int r = 0; r < 8; r++) {
            ull xp = pack2(xw[r]);
#pragma unroll
            for (int p = 0; p < 4; p++) acc[r][p] = ffma2(xp, wcur[p], acc[r][p]);
        }

        // slide window by 2 time steps (renamed under full unroll)
#pragma unroll
        for (int r = 7; r >= 2; r--) xw[r] = xw[r - 2];
        xw[1] = n1; xw[0] = n0;
#pragma unroll
        for (int p = 0; p < 4; p++) wcur[p] = wnext[p];
    }

    // ---- ReLU + vectorized store ----
#pragma unroll
    for (int r = 0; r < 8; r++) {
        float4 v[2];
        float* vf = reinterpret_cast<float*>(v);
        const float* af = reinterpret_cast<const float*>(acc[r]);
#pragma unroll
        for (int k = 0; k < 8; k++) vf[k] = fmaxf(af[k], 0.f);
        float4* o = reinterpret_cast<float4*>(out + (long)(t0 + r) * (NI * F)
                                              + (ib + lane) * F + fh * 8);
        o[0] = v[0];
        o[1] = v[1];
    }
}

extern "C" void kernel_launch(void* const* d_in, const int* in_sizes, int n_in,
                              void* d_out, int out_size) {
    const float* x    = (const float*)d_in[0];
    const float* w    = (const float*)d_in[1];
    const float* bias = (const float*)d_in[2];
    float* out        = (float*)d_out;

    prep_kernel<<<1, 32>>>(w);

    dim3 grid(NI / 128, T_DIM / 8);
    conv_kernel<<<grid, 256>>>(x, bias, out);
}